// round 14
// baseline (speedup 1.0000x reference)
#include <cuda_runtime.h>
#include <math.h>
#include <stdint.h>

// Problem constants
#define BSZ 2
#define LSEQ 2048
#define DMODEL 2048
#define NHEAD 32
#define HDIM 64
#define MROWS (BSZ * LSEQ)     // 4096
#define NQKV (3 * DMODEL)      // 6144

// Scratch (device globals)
__device__ float g_qkv[(size_t)MROWS * NQKV];     // raw f32 QKV
__device__ float g_x [(size_t)MROWS * DMODEL];    // tf32 bits of x
__device__ float g_wq[(size_t)NQKV * DMODEL];     // tf32 bits of wqkv
__device__ float g_wo[(size_t)DMODEL * DMODEL];   // tf32 bits of wo
__device__ float g_q[(size_t)MROWS * DMODEL];     // tf32 bits, q*scale, [B,H,L,hd]
__device__ float g_k[(size_t)MROWS * DMODEL];     // tf32 bits, [B,H,L,hd]
__device__ float g_v[(size_t)MROWS * DMODEL];     // tf32 bits, [B,H,tile,hd,64] (transposed tiles)
__device__ float g_ao[(size_t)MROWS * DMODEL];    // tf32 bits, [B*L, H*hd]

__device__ __forceinline__ uint32_t f2tf32(float x) {
    uint32_t y;
    asm("cvt.rna.tf32.f32 %0, %1;" : "=r"(y) : "f"(x));
    return y;
}
__device__ __forceinline__ float ex2f(float x) {
    float y;
    asm("ex2.approx.f32 %0, %1;" : "=f"(y) : "f"(x));
    return y;
}
__device__ __forceinline__ void mma_tf32(float* d, const uint32_t* a,
                                         const uint32_t* b) {
    asm volatile(
        "mma.sync.aligned.m16n8k8.row.col.f32.tf32.tf32.f32 "
        "{%0,%1,%2,%3}, {%4,%5,%6,%7}, {%8,%9}, {%0,%1,%2,%3};"
        : "+f"(d[0]), "+f"(d[1]), "+f"(d[2]), "+f"(d[3])
        : "r"(a[0]), "r"(a[1]), "r"(a[2]), "r"(a[3]), "r"(b[0]), "r"(b[1]));
}
__device__ __forceinline__ uint32_t sm_u32(const void* p) {
    uint32_t a;
    asm("{ .reg .u64 t; cvta.to.shared.u64 t, %1; cvt.u32.u64 %0, t; }"
        : "=r"(a) : "l"(p));
    return a;
}
__device__ __forceinline__ void cp16(uint32_t dst, const void* src) {
    asm volatile("cp.async.cg.shared.global [%0], [%1], 16;" :: "r"(dst), "l"(src));
}
#define CP_COMMIT() asm volatile("cp.async.commit_group;")
#define CP_WAIT0()  asm volatile("cp.async.wait_group 0;")

// ---------------------------------------------------------------------------
// Elementwise tf32-rna pre-convert (stores tf32 bit patterns as float)
// ---------------------------------------------------------------------------
__global__ void __launch_bounds__(256)
k_cvt(const float* __restrict__ in, float* __restrict__ out, int n4) {
    int i = blockIdx.x * blockDim.x + threadIdx.x;
    if (i >= n4) return;
    float4 v = *(const float4*)(in + (size_t)i * 4);
    uint4 u = make_uint4(f2tf32(v.x), f2tf32(v.y), f2tf32(v.z), f2tf32(v.w));
    *(uint4*)(out + (size_t)i * 4) = u;
}

// ---------------------------------------------------------------------------
// TF32 GEMM v3 (NT): C[M,N] = A[M,K] @ B[N,K]^T. Inputs are tf32 bits.
// 128x128 block, 4 warps (2x2), 64x64 warp tile, BK=32, cp.async double
// buffer, no cvt in mainloop, stride-40 smem (conflict-free LDS.64),
// one barrier per stage. K-permuted mma slots.
// ---------------------------------------------------------------------------
#define GSTR 40
#define GEMM_SMEM (4 * 128 * GSTR * 4)   // A[2]+B[2] = 81920 B

__global__ void __launch_bounds__(128)
k_gemm_tf32(const uint32_t* __restrict__ A, const uint32_t* __restrict__ B,
            float* __restrict__ C, int N, int K) {
    extern __shared__ uint32_t gsm[];
    // A buffer b: gsm + b*128*GSTR ; B buffer b: gsm + (2+b)*128*GSTR
    const uint32_t smb = sm_u32(gsm);

    const int tid  = threadIdx.x;
    const int warp = tid >> 5, lane = tid & 31;
    const int row0 = blockIdx.y * 128;
    const int col0 = blockIdx.x * 128;
    const int wr = warp & 1;
    const int wc = warp >> 1;
    const int g  = lane >> 2;
    const int c  = lane & 3;

    // staging: 1024 16B-chunks per matrix per stage, 8 per thread
    const int st_r  = tid >> 3;          // +16 per i? no: u = tid + i*128, r = u>>3
    const int st_c4 = (tid & 7) * 4;

    float acc[4][8][4];
#pragma unroll
    for (int mt = 0; mt < 4; mt++)
#pragma unroll
        for (int nt = 0; nt < 8; nt++)
#pragma unroll
            for (int i = 0; i < 4; i++) acc[mt][nt][i] = 0.f;

    const int nst = K / 32;

    // prologue: stage 0
#pragma unroll
    for (int i = 0; i < 8; i++) {
        int r = st_r + i * 16;
        cp16(smb + (r * GSTR + st_c4) * 4, A + (size_t)(row0 + r) * K + st_c4);
        cp16(smb + ((2 * 128 + r) * GSTR + st_c4) * 4, B + (size_t)(col0 + r) * K + st_c4);
    }
    CP_COMMIT();

    for (int s = 0; s < nst; s++) {
        CP_WAIT0();
        __syncthreads();

        if (s + 1 < nst) {
            const int b1 = (s + 1) & 1;
            const int k1 = (s + 1) * 32;
#pragma unroll
            for (int i = 0; i < 8; i++) {
                int r = st_r + i * 16;
                cp16(smb + ((b1 * 128 + r) * GSTR + st_c4) * 4,
                     A + (size_t)(row0 + r) * K + k1 + st_c4);
                cp16(smb + (((2 + b1) * 128 + r) * GSTR + st_c4) * 4,
                     B + (size_t)(col0 + r) * K + k1 + st_c4);
            }
            CP_COMMIT();
        }

        const int b = s & 1;
        const uint32_t (*As)[GSTR] = (const uint32_t(*)[GSTR])(gsm + b * 128 * GSTR);
        const uint32_t (*Bs)[GSTR] = (const uint32_t(*)[GSTR])(gsm + (2 + b) * 128 * GSTR);

#pragma unroll
        for (int ks = 0; ks < 4; ks++) {
            uint32_t af[4][4];
#pragma unroll
            for (int mt = 0; mt < 4; mt++) {
                int rr = wr * 64 + mt * 16;
                uint2 x0 = *(const uint2*)&As[rr + g][ks * 8 + 2 * c];
                uint2 x1 = *(const uint2*)&As[rr + g + 8][ks * 8 + 2 * c];
                af[mt][0] = x0.x; af[mt][2] = x0.y;
                af[mt][1] = x1.x; af[mt][3] = x1.y;
            }
#pragma unroll
            for (int nt = 0; nt < 8; nt++) {
                int cc = wc * 64 + nt * 8;
                uint2 y = *(const uint2*)&Bs[cc + g][ks * 8 + 2 * c];
                uint32_t bf[2] = {y.x, y.y};
#pragma unroll
                for (int mt = 0; mt < 4; mt++)
                    mma_tf32(acc[mt][nt], af[mt], bf);
            }
        }
    }

    // Epilogue
#pragma unroll
    for (int mt = 0; mt < 4; mt++) {
        int r0 = row0 + wr * 64 + mt * 16 + g;
#pragma unroll
        for (int nt = 0; nt < 8; nt++) {
            int cc = col0 + wc * 64 + nt * 8 + c * 2;
            *(float2*)&C[(size_t)r0 * N + cc] = make_float2(acc[mt][nt][0], acc[mt][nt][1]);
            *(float2*)&C[(size_t)(r0 + 8) * N + cc] = make_float2(acc[mt][nt][2], acc[mt][nt][3]);
        }
    }
}

// ---------------------------------------------------------------------------
// RoPE + split. Writes tf32 BIT PATTERNS:
//  g_q = tf32(qscale * rot(q))   [B,H,L,hd], qscale = 0.125*log2(e)
//  g_k = tf32(rot(k))            [B,H,L,hd]
//  g_v = tf32(v) TRANSPOSED per 64-token tile: [B,H, t, hd, 64]
// ---------------------------------------------------------------------------
__global__ void __launch_bounds__(256)
k_rope_split() {
    int idx = blockIdx.x * blockDim.x + threadIdx.x;
    const int d  = idx & 31;
    const int h  = (idx >> 5) & 31;
    const int ml = idx >> 10;
    if (ml >= MROWS) return;
    const int l  = ml & (LSEQ - 1);
    const int b  = ml >> 11;
    const float qscale = 0.125f * 1.4426950408889634f;

    const size_t base = (size_t)ml * NQKV + (size_t)h * HDIM;
    float q1 = g_qkv[base + d];
    float q2 = g_qkv[base + d + 32];
    float k1 = g_qkv[base + DMODEL + d];
    float k2 = g_qkv[base + DMODEL + d + 32];
    float v1 = g_qkv[base + 2 * DMODEL + d];
    float v2 = g_qkv[base + 2 * DMODEL + d + 32];

    float inv_freq = exp2f(-9.0f * (float)d / 32.0f);
    float f = (float)l * inv_freq;
    float s, cc;
    sincosf(f, &s, &cc);

    const int bh = b * NHEAD + h;
    const size_t obase = ((size_t)bh * LSEQ + l) * HDIM;
    ((uint32_t*)g_q)[obase + d]      = f2tf32(qscale * (q1 * cc - q2 * s));
    ((uint32_t*)g_q)[obase + d + 32] = f2tf32(qscale * (q2 * cc + q1 * s));
    ((uint32_t*)g_k)[obase + d]      = f2tf32(k1 * cc - k2 * s);
    ((uint32_t*)g_k)[obase + d + 32] = f2tf32(k2 * cc + k1 * s);

    const int t = l >> 6, lc = l & 63;
    const size_t vbase = (((size_t)bh * 32 + t) * HDIM) * 64 + lc;
    ((uint32_t*)g_v)[vbase + (size_t)d * 64]        = f2tf32(v1);
    ((uint32_t*)g_v)[vbase + (size_t)(d + 32) * 64] = f2tf32(v2);
}

// ---------------------------------------------------------------------------
// Flash attention v4: inputs pre-tf32 (no cvt), V pre-transposed (no smem
// transpose pass), 1 barrier per k-tile, cp.async double buffer.
// Grid: (L/128, B*H). Block: 256 threads / 8 warps.
// smem: Ks[2][64][72] + Vt[2][64][72]; Q staging aliases Ks.
// ---------------------------------------------------------------------------
#define FKSTR 72
#define FA_SMEM (4 * 64 * FKSTR * 4)   // 73728 B

__global__ void __launch_bounds__(256)
k_flash_attn_mma() {
    extern __shared__ uint32_t sm[];
    const uint32_t smb = sm_u32(sm);

    const int tid  = threadIdx.x;
    const int warp = tid >> 5, lane = tid & 31;
    const int g = lane >> 2, c = lane & 3;
    const int qt = gridDim.x - 1 - blockIdx.x;
    const int bh = blockIdx.y;
    const int rb = warp * 16;

    // ---- Prologue: stage Q (tf32 bits) into Ks-alias, build A-frags --------
    uint32_t (*Qs)[FKSTR] = (uint32_t(*)[FKSTR])sm;   // 128 x 72, aliases Ks
    const uint32_t* Qg =
        (const uint32_t*)g_q + ((size_t)bh * LSEQ + (size_t)qt * 128) * HDIM;
#pragma unroll
    for (int i = 0; i < 8; i++) {
        int u = tid + i * 256;
        int r = u >> 4, c4 = (u & 15) * 4;
        *(uint4*)&Qs[r][c4] = *(const uint4*)(Qg + (size_t)r * HDIM + c4);
    }
    __syncthreads();

    uint32_t af[8][4];
#pragma unroll
    for (int kc = 0; kc < 8; kc++) {
        uint2 a0 = *(const uint2*)&Qs[rb + g][kc * 8 + 2 * c];
        uint2 a1 = *(const uint2*)&Qs[rb + g + 8][kc * 8 + 2 * c];
        af[kc][0] = a0.x; af[kc][2] = a0.y;
        af[kc][1] = a1.x; af[kc][3] = a1.y;
    }
    __syncthreads();   // Q region dead

    const int cp_r  = tid >> 4;
    const int cp_c4 = (tid & 15) * 4;

    const uint32_t* Kg0 = (const uint32_t*)g_k + (size_t)bh * LSEQ * HDIM;
    const uint32_t* Vg0 = (const uint32_t*)g_v + (size_t)bh * 32 * 4096;

    // issue tile 0 into buffer 0
#pragma unroll
    for (int i = 0; i < 4; i++) {
        int r = cp_r + i * 16;
        cp16(smb + (r * FKSTR + cp_c4) * 4, Kg0 + (size_t)r * HDIM + cp_c4);
        cp16(smb + ((128 + r) * FKSTR + cp_c4) * 4, Vg0 + (size_t)r * 64 + cp_c4);
    }
    CP_COMMIT();

    float oacc[8][4];
#pragma unroll
    for (int nt = 0; nt < 8; nt++)
#pragma unroll
        for (int i = 0; i < 4; i++) oacc[nt][i] = 0.f;
    float m0 = -1e30f, m1 = -1e30f, l0 = 0.f, l1 = 0.f;

    const int ktmax = 2 * qt + 1;
    for (int kt = 0; kt <= ktmax; ++kt) {
        const int b = kt & 1;
        CP_WAIT0();
        __syncthreads();

        if (kt < ktmax) {
            const uint32_t* Kg = Kg0 + (size_t)(kt + 1) * 64 * HDIM;
            const uint32_t* Vg = Vg0 + (size_t)(kt + 1) * 4096;
            const int b1 = b ^ 1;
#pragma unroll
            for (int i = 0; i < 4; i++) {
                int r = cp_r + i * 16;
                cp16(smb + ((b1 * 64 + r) * FKSTR + cp_c4) * 4,
                     Kg + (size_t)r * HDIM + cp_c4);
                cp16(smb + ((128 + b1 * 64 + r) * FKSTR + cp_c4) * 4,
                     Vg + (size_t)r * 64 + cp_c4);
            }
            CP_COMMIT();
        }

        const uint32_t (*Ks)[FKSTR] = (const uint32_t(*)[FKSTR])(sm + b * 64 * FKSTR);
        const uint32_t (*Vt)[FKSTR] = (const uint32_t(*)[FKSTR])(sm + (128 + b * 64) * FKSTR);

        // S = Q @ K^T (log2 domain, scale pre-folded into Q)
        float s[8][4];
#pragma unroll
        for (int nt = 0; nt < 8; nt++) {
            s[nt][0] = s[nt][1] = s[nt][2] = s[nt][3] = 0.f;
#pragma unroll
            for (int kc = 0; kc < 8; kc++) {
                uint2 bb = *(const uint2*)&Ks[nt * 8 + g][kc * 8 + 2 * c];
                uint32_t bf[2] = {bb.x, bb.y};
                mma_tf32(s[nt], af[kc], bf);
            }
        }

        if (kt >= 2 * qt) {
            int qr0 = qt * 128 + rb + g;
            int qr1 = qr0 + 8;
#pragma unroll
            for (int nt = 0; nt < 8; nt++) {
                int col = kt * 64 + nt * 8 + 2 * c;
                if (col > qr0)     s[nt][0] = -1e30f;
                if (col + 1 > qr0) s[nt][1] = -1e30f;
                if (col > qr1)     s[nt][2] = -1e30f;
                if (col + 1 > qr1) s[nt][3] = -1e30f;
            }
        }

        float tm0 = -1e30f, tm1 = -1e30f;
#pragma unroll
        for (int nt = 0; nt < 8; nt++) {
            tm0 = fmaxf(tm0, fmaxf(s[nt][0], s[nt][1]));
            tm1 = fmaxf(tm1, fmaxf(s[nt][2], s[nt][3]));
        }
        tm0 = fmaxf(tm0, __shfl_xor_sync(0xffffffff, tm0, 1));
        tm0 = fmaxf(tm0, __shfl_xor_sync(0xffffffff, tm0, 2));
        tm1 = fmaxf(tm1, __shfl_xor_sync(0xffffffff, tm1, 1));
        tm1 = fmaxf(tm1, __shfl_xor_sync(0xffffffff, tm1, 2));
        float nm0 = fmaxf(m0, tm0);
        float nm1 = fmaxf(m1, tm1);
        float cr0 = ex2f(m0 - nm0);
        float cr1 = ex2f(m1 - nm1);
        m0 = nm0; m1 = nm1;
        l0 *= cr0; l1 *= cr1;
#pragma unroll
        for (int nt = 0; nt < 8; nt++) {
            oacc[nt][0] *= cr0; oacc[nt][1] *= cr0;
            oacc[nt][2] *= cr1; oacc[nt][3] *= cr1;
        }
#pragma unroll
        for (int nt = 0; nt < 8; nt++) {
            s[nt][0] = ex2f(s[nt][0] - nm0);
            s[nt][1] = ex2f(s[nt][1] - nm0);
            s[nt][2] = ex2f(s[nt][2] - nm1);
            s[nt][3] = ex2f(s[nt][3] - nm1);
            l0 += s[nt][0] + s[nt][1];
            l1 += s[nt][2] + s[nt][3];
        }

        // O += P @ V (P in registers, k-permuted)
#pragma unroll
        for (int kc = 0; kc < 8; kc++) {
            uint32_t pa[4];
            pa[0] = f2tf32(s[kc][0]);
            pa[1] = f2tf32(s[kc][2]);
            pa[2] = f2tf32(s[kc][1]);
            pa[3] = f2tf32(s[kc][3]);
#pragma unroll
            for (int nt = 0; nt < 8; nt++) {
                uint2 bb = *(const uint2*)&Vt[nt * 8 + g][kc * 8 + 2 * c];
                uint32_t bf[2] = {bb.x, bb.y};
                mma_tf32(oacc[nt], pa, bf);
            }
        }
    }

    l0 += __shfl_xor_sync(0xffffffff, l0, 1);
    l0 += __shfl_xor_sync(0xffffffff, l0, 2);
    l1 += __shfl_xor_sync(0xffffffff, l1, 1);
    l1 += __shfl_xor_sync(0xffffffff, l1, 2);
    const float inv0 = 1.f / l0;
    const float inv1 = 1.f / l1;

    const int bb = bh >> 5, h = bh & 31;
    const int qr = qt * 128 + rb + g;
    uint32_t* o0 = (uint32_t*)g_ao + ((size_t)(bb * LSEQ + qr)) * DMODEL + (size_t)h * HDIM;
    uint32_t* o1 = o0 + (size_t)8 * DMODEL;
#pragma unroll
    for (int nt = 0; nt < 8; nt++) {
        uint2 r0 = make_uint2(f2tf32(oacc[nt][0] * inv0), f2tf32(oacc[nt][1] * inv0));
        uint2 r1 = make_uint2(f2tf32(oacc[nt][2] * inv1), f2tf32(oacc[nt][3] * inv1));
        *(uint2*)(o0 + nt * 8 + 2 * c) = r0;
        *(uint2*)(o1 + nt * 8 + 2 * c) = r1;
    }
}

// ---------------------------------------------------------------------------
extern "C" void kernel_launch(void* const* d_in, const int* in_sizes, int n_in,
                              void* d_out, int out_size) {
    const float* x    = (const float*)d_in[0];
    const float* wqkv = (const float*)d_in[1];
    const float* wo   = (const float*)d_in[2];
    float* out        = (float*)d_out;

    float *qkv, *xc, *wqc, *woc, *ao;
    cudaGetSymbolAddress((void**)&qkv, g_qkv);
    cudaGetSymbolAddress((void**)&xc,  g_x);
    cudaGetSymbolAddress((void**)&wqc, g_wq);
    cudaGetSymbolAddress((void**)&woc, g_wo);
    cudaGetSymbolAddress((void**)&ao,  g_ao);

    static bool attr_set = false;
    if (!attr_set) {
        cudaFuncSetAttribute(k_flash_attn_mma,
                             cudaFuncAttributeMaxDynamicSharedMemorySize, FA_SMEM);
        cudaFuncSetAttribute(k_gemm_tf32,
                             cudaFuncAttributeMaxDynamicSharedMemorySize, GEMM_SMEM);
        attr_set = true;
    }

    // 0) pre-convert inputs to tf32 bits
    {
        int n4;
        n4 = MROWS * DMODEL / 4;  k_cvt<<<(n4 + 255) / 256, 256>>>(x, xc, n4);
        n4 = NQKV * DMODEL / 4;   k_cvt<<<(n4 + 255) / 256, 256>>>(wqkv, wqc, n4);
        n4 = DMODEL * DMODEL / 4; k_cvt<<<(n4 + 255) / 256, 256>>>(wo, woc, n4);
    }
    // 1) QKV projection
    {
        dim3 grid(NQKV / 128, MROWS / 128);
        k_gemm_tf32<<<grid, 128, GEMM_SMEM>>>((const uint32_t*)xc,
                                              (const uint32_t*)wqc, qkv,
                                              NQKV, DMODEL);
    }
    // 2) RoPE + split (+ tf32 conversion + V tile transpose)
    {
        int total = MROWS * NHEAD * 32;
        k_rope_split<<<(total + 255) / 256, 256>>>();
    }
    // 3) Flash attention
    {
        dim3 grid(LSEQ / 128, BSZ * NHEAD);
        k_flash_attn_mma<<<grid, 256, FA_SMEM>>>();
    }
    // 4) Output projection
    {
        dim3 grid(DMODEL / 128, MROWS / 128);
        k_gemm_tf32<<<grid, 128, GEMM_SMEM>>>((const uint32_t*)ao,
                                              (const uint32_t*)woc, out,
                                              DMODEL, DMODEL);
    }
}

// round 15
// speedup vs baseline: 1.5405x; 1.5405x over previous
#include <cuda_runtime.h>
#include <math.h>
#include <stdint.h>

// Problem constants
#define BSZ 2
#define LSEQ 2048
#define DMODEL 2048
#define NHEAD 32
#define HDIM 64
#define MROWS (BSZ * LSEQ)     // 4096
#define NQKV (3 * DMODEL)      // 6144

// Scratch (device globals)
__device__ float g_qkv[(size_t)MROWS * NQKV];     // raw f32 QKV
__device__ float g_x [(size_t)MROWS * DMODEL];    // tf32 bits of x
__device__ float g_wq[(size_t)NQKV * DMODEL];     // tf32 bits of wqkv
__device__ float g_wo[(size_t)DMODEL * DMODEL];   // tf32 bits of wo
__device__ float g_q[(size_t)MROWS * DMODEL];     // tf32 bits, q*scale, [B,H,L,hd]
__device__ float g_k[(size_t)MROWS * DMODEL];     // tf32 bits, [B,H,L,hd]
__device__ float g_v[(size_t)MROWS * DMODEL];     // tf32 bits, [B,H,tile,hd,64] (transposed tiles)
__device__ float g_ao[(size_t)MROWS * DMODEL];    // tf32 bits, [B*L, H*hd]

__device__ __forceinline__ uint32_t f2tf32(float x) {
    uint32_t y;
    asm("cvt.rna.tf32.f32 %0, %1;" : "=r"(y) : "f"(x));
    return y;
}
__device__ __forceinline__ float ex2f(float x) {
    float y;
    asm("ex2.approx.f32 %0, %1;" : "=f"(y) : "f"(x));
    return y;
}
__device__ __forceinline__ void mma_tf32(float* d, const uint32_t* a,
                                         const uint32_t* b) {
    asm volatile(
        "mma.sync.aligned.m16n8k8.row.col.f32.tf32.tf32.f32 "
        "{%0,%1,%2,%3}, {%4,%5,%6,%7}, {%8,%9}, {%0,%1,%2,%3};"
        : "+f"(d[0]), "+f"(d[1]), "+f"(d[2]), "+f"(d[3])
        : "r"(a[0]), "r"(a[1]), "r"(a[2]), "r"(a[3]), "r"(b[0]), "r"(b[1]));
}
__device__ __forceinline__ uint32_t sm_u32(const void* p) {
    uint32_t a;
    asm("{ .reg .u64 t; cvta.to.shared.u64 t, %1; cvt.u32.u64 %0, t; }"
        : "=r"(a) : "l"(p));
    return a;
}
__device__ __forceinline__ void cp16(uint32_t dst, const void* src) {
    asm volatile("cp.async.cg.shared.global [%0], [%1], 16;" :: "r"(dst), "l"(src));
}
#define CP_COMMIT() asm volatile("cp.async.commit_group;")
#define CP_WAIT0()  asm volatile("cp.async.wait_group 0;")

// ---------------------------------------------------------------------------
// Elementwise tf32-rna pre-convert (stores tf32 bit patterns as float)
// ---------------------------------------------------------------------------
__global__ void __launch_bounds__(256)
k_cvt(const float* __restrict__ in, float* __restrict__ out, int n4) {
    int i = blockIdx.x * blockDim.x + threadIdx.x;
    if (i >= n4) return;
    float4 v = *(const float4*)(in + (size_t)i * 4);
    uint4 u = make_uint4(f2tf32(v.x), f2tf32(v.y), f2tf32(v.z), f2tf32(v.w));
    *(uint4*)(out + (size_t)i * 4) = u;
}

// ---------------------------------------------------------------------------
// TF32 GEMM v3 (NT): C[M,N] = A[M,K] @ B[N,K]^T. Inputs are tf32 bits.
// 128x128 block, 4 warps (2x2), 64x64 warp tile, BK=32, cp.async double
// buffer, no cvt in mainloop, stride-40 smem (conflict-free LDS.64),
// one barrier per stage. K-permuted mma slots.
// ---------------------------------------------------------------------------
#define GSTR 40
#define GEMM_SMEM (4 * 128 * GSTR * 4)   // A[2]+B[2] = 81920 B

__global__ void __launch_bounds__(128)
k_gemm_tf32(const uint32_t* __restrict__ A, const uint32_t* __restrict__ B,
            float* __restrict__ C, int N, int K) {
    extern __shared__ uint32_t gsm[];
    // A buffer b: gsm + b*128*GSTR ; B buffer b: gsm + (2+b)*128*GSTR
    const uint32_t smb = sm_u32(gsm);

    const int tid  = threadIdx.x;
    const int warp = tid >> 5, lane = tid & 31;
    const int row0 = blockIdx.y * 128;
    const int col0 = blockIdx.x * 128;
    const int wr = warp & 1;
    const int wc = warp >> 1;
    const int g  = lane >> 2;
    const int c  = lane & 3;

    // staging: 1024 16B-chunks per matrix per stage, 8 per thread
    const int st_r  = tid >> 3;          // +16 per i? no: u = tid + i*128, r = u>>3
    const int st_c4 = (tid & 7) * 4;

    float acc[4][8][4];
#pragma unroll
    for (int mt = 0; mt < 4; mt++)
#pragma unroll
        for (int nt = 0; nt < 8; nt++)
#pragma unroll
            for (int i = 0; i < 4; i++) acc[mt][nt][i] = 0.f;

    const int nst = K / 32;

    // prologue: stage 0
#pragma unroll
    for (int i = 0; i < 8; i++) {
        int r = st_r + i * 16;
        cp16(smb + (r * GSTR + st_c4) * 4, A + (size_t)(row0 + r) * K + st_c4);
        cp16(smb + ((2 * 128 + r) * GSTR + st_c4) * 4, B + (size_t)(col0 + r) * K + st_c4);
    }
    CP_COMMIT();

    for (int s = 0; s < nst; s++) {
        CP_WAIT0();
        __syncthreads();

        if (s + 1 < nst) {
            const int b1 = (s + 1) & 1;
            const int k1 = (s + 1) * 32;
#pragma unroll
            for (int i = 0; i < 8; i++) {
                int r = st_r + i * 16;
                cp16(smb + ((b1 * 128 + r) * GSTR + st_c4) * 4,
                     A + (size_t)(row0 + r) * K + k1 + st_c4);
                cp16(smb + (((2 + b1) * 128 + r) * GSTR + st_c4) * 4,
                     B + (size_t)(col0 + r) * K + k1 + st_c4);
            }
            CP_COMMIT();
        }

        const int b = s & 1;
        const uint32_t (*As)[GSTR] = (const uint32_t(*)[GSTR])(gsm + b * 128 * GSTR);
        const uint32_t (*Bs)[GSTR] = (const uint32_t(*)[GSTR])(gsm + (2 + b) * 128 * GSTR);

#pragma unroll
        for (int ks = 0; ks < 4; ks++) {
            uint32_t af[4][4];
#pragma unroll
            for (int mt = 0; mt < 4; mt++) {
                int rr = wr * 64 + mt * 16;
                uint2 x0 = *(const uint2*)&As[rr + g][ks * 8 + 2 * c];
                uint2 x1 = *(const uint2*)&As[rr + g + 8][ks * 8 + 2 * c];
                af[mt][0] = x0.x; af[mt][2] = x0.y;
                af[mt][1] = x1.x; af[mt][3] = x1.y;
            }
#pragma unroll
            for (int nt = 0; nt < 8; nt++) {
                int cc = wc * 64 + nt * 8;
                uint2 y = *(const uint2*)&Bs[cc + g][ks * 8 + 2 * c];
                uint32_t bf[2] = {y.x, y.y};
#pragma unroll
                for (int mt = 0; mt < 4; mt++)
                    mma_tf32(acc[mt][nt], af[mt], bf);
            }
        }
    }

    // Epilogue
#pragma unroll
    for (int mt = 0; mt < 4; mt++) {
        int r0 = row0 + wr * 64 + mt * 16 + g;
#pragma unroll
        for (int nt = 0; nt < 8; nt++) {
            int cc = col0 + wc * 64 + nt * 8 + c * 2;
            *(float2*)&C[(size_t)r0 * N + cc] = make_float2(acc[mt][nt][0], acc[mt][nt][1]);
            *(float2*)&C[(size_t)(r0 + 8) * N + cc] = make_float2(acc[mt][nt][2], acc[mt][nt][3]);
        }
    }
}

// ---------------------------------------------------------------------------
// RoPE + split. Writes tf32 BIT PATTERNS:
//  g_q = tf32(qscale * rot(q))   [B,H,L,hd], qscale = 0.125*log2(e)
//  g_k = tf32(rot(k))            [B,H,L,hd]
//  g_v = tf32(v) TRANSPOSED per 64-token tile: [B,H, t, hd, 64]
// ---------------------------------------------------------------------------
__global__ void __launch_bounds__(256)
k_rope_split() {
    int idx = blockIdx.x * blockDim.x + threadIdx.x;
    const int d  = idx & 31;
    const int h  = (idx >> 5) & 31;
    const int ml = idx >> 10;
    if (ml >= MROWS) return;
    const int l  = ml & (LSEQ - 1);
    const int b  = ml >> 11;
    const float qscale = 0.125f * 1.4426950408889634f;

    const size_t base = (size_t)ml * NQKV + (size_t)h * HDIM;
    float q1 = g_qkv[base + d];
    float q2 = g_qkv[base + d + 32];
    float k1 = g_qkv[base + DMODEL + d];
    float k2 = g_qkv[base + DMODEL + d + 32];
    float v1 = g_qkv[base + 2 * DMODEL + d];
    float v2 = g_qkv[base + 2 * DMODEL + d + 32];

    float inv_freq = exp2f(-9.0f * (float)d / 32.0f);
    float f = (float)l * inv_freq;
    float s, cc;
    sincosf(f, &s, &cc);

    const int bh = b * NHEAD + h;
    const size_t obase = ((size_t)bh * LSEQ + l) * HDIM;
    ((uint32_t*)g_q)[obase + d]      = f2tf32(qscale * (q1 * cc - q2 * s));
    ((uint32_t*)g_q)[obase + d + 32] = f2tf32(qscale * (q2 * cc + q1 * s));
    ((uint32_t*)g_k)[obase + d]      = f2tf32(k1 * cc - k2 * s);
    ((uint32_t*)g_k)[obase + d + 32] = f2tf32(k2 * cc + k1 * s);

    const int t = l >> 6, lc = l & 63;
    const size_t vbase = (((size_t)bh * 32 + t) * HDIM) * 64 + lc;
    ((uint32_t*)g_v)[vbase + (size_t)d * 64]        = f2tf32(v1);
    ((uint32_t*)g_v)[vbase + (size_t)(d + 32) * 64] = f2tf32(v2);
}

// ---------------------------------------------------------------------------
// Flash attention v4: inputs pre-tf32 (no cvt), V pre-transposed (no smem
// transpose pass), 1 barrier per k-tile, cp.async double buffer.
// Grid: (L/128, B*H). Block: 256 threads / 8 warps.
// smem: Ks[2][64][72] + Vt[2][64][72]; Q staging aliases Ks.
// ---------------------------------------------------------------------------
#define FKSTR 72
#define FA_SMEM (4 * 64 * FKSTR * 4)   // 73728 B

__global__ void __launch_bounds__(256)
k_flash_attn_mma() {
    extern __shared__ uint32_t sm[];
    const uint32_t smb = sm_u32(sm);

    const int tid  = threadIdx.x;
    const int warp = tid >> 5, lane = tid & 31;
    const int g = lane >> 2, c = lane & 3;
    const int qt = gridDim.x - 1 - blockIdx.x;
    const int bh = blockIdx.y;
    const int rb = warp * 16;

    // ---- Prologue: stage Q (tf32 bits) into Ks-alias, build A-frags --------
    uint32_t (*Qs)[FKSTR] = (uint32_t(*)[FKSTR])sm;   // 128 x 72, aliases Ks
    const uint32_t* Qg =
        (const uint32_t*)g_q + ((size_t)bh * LSEQ + (size_t)qt * 128) * HDIM;
#pragma unroll
    for (int i = 0; i < 8; i++) {
        int u = tid + i * 256;
        int r = u >> 4, c4 = (u & 15) * 4;
        *(uint4*)&Qs[r][c4] = *(const uint4*)(Qg + (size_t)r * HDIM + c4);
    }
    __syncthreads();

    uint32_t af[8][4];
#pragma unroll
    for (int kc = 0; kc < 8; kc++) {
        uint2 a0 = *(const uint2*)&Qs[rb + g][kc * 8 + 2 * c];
        uint2 a1 = *(const uint2*)&Qs[rb + g + 8][kc * 8 + 2 * c];
        af[kc][0] = a0.x; af[kc][2] = a0.y;
        af[kc][1] = a1.x; af[kc][3] = a1.y;
    }
    __syncthreads();   // Q region dead

    const int cp_r  = tid >> 4;
    const int cp_c4 = (tid & 15) * 4;

    const uint32_t* Kg0 = (const uint32_t*)g_k + (size_t)bh * LSEQ * HDIM;
    const uint32_t* Vg0 = (const uint32_t*)g_v + (size_t)bh * 32 * 4096;

    // issue tile 0 into buffer 0
#pragma unroll
    for (int i = 0; i < 4; i++) {
        int r = cp_r + i * 16;
        cp16(smb + (r * FKSTR + cp_c4) * 4, Kg0 + (size_t)r * HDIM + cp_c4);
        cp16(smb + ((128 + r) * FKSTR + cp_c4) * 4, Vg0 + (size_t)r * 64 + cp_c4);
    }
    CP_COMMIT();

    float oacc[8][4];
#pragma unroll
    for (int nt = 0; nt < 8; nt++)
#pragma unroll
        for (int i = 0; i < 4; i++) oacc[nt][i] = 0.f;
    float m0 = -1e30f, m1 = -1e30f, l0 = 0.f, l1 = 0.f;

    const int ktmax = 2 * qt + 1;
    for (int kt = 0; kt <= ktmax; ++kt) {
        const int b = kt & 1;
        CP_WAIT0();
        __syncthreads();

        if (kt < ktmax) {
            const uint32_t* Kg = Kg0 + (size_t)(kt + 1) * 64 * HDIM;
            const uint32_t* Vg = Vg0 + (size_t)(kt + 1) * 4096;
            const int b1 = b ^ 1;
#pragma unroll
            for (int i = 0; i < 4; i++) {
                int r = cp_r + i * 16;
                cp16(smb + ((b1 * 64 + r) * FKSTR + cp_c4) * 4,
                     Kg + (size_t)r * HDIM + cp_c4);
                cp16(smb + ((128 + b1 * 64 + r) * FKSTR + cp_c4) * 4,
                     Vg + (size_t)r * 64 + cp_c4);
            }
            CP_COMMIT();
        }

        const uint32_t (*Ks)[FKSTR] = (const uint32_t(*)[FKSTR])(sm + b * 64 * FKSTR);
        const uint32_t (*Vt)[FKSTR] = (const uint32_t(*)[FKSTR])(sm + (128 + b * 64) * FKSTR);

        // S = Q @ K^T (log2 domain, scale pre-folded into Q)
        float s[8][4];
#pragma unroll
        for (int nt = 0; nt < 8; nt++) {
            s[nt][0] = s[nt][1] = s[nt][2] = s[nt][3] = 0.f;
#pragma unroll
            for (int kc = 0; kc < 8; kc++) {
                uint2 bb = *(const uint2*)&Ks[nt * 8 + g][kc * 8 + 2 * c];
                uint32_t bf[2] = {bb.x, bb.y};
                mma_tf32(s[nt], af[kc], bf);
            }
        }

        if (kt >= 2 * qt) {
            int qr0 = qt * 128 + rb + g;
            int qr1 = qr0 + 8;
#pragma unroll
            for (int nt = 0; nt < 8; nt++) {
                int col = kt * 64 + nt * 8 + 2 * c;
                if (col > qr0)     s[nt][0] = -1e30f;
                if (col + 1 > qr0) s[nt][1] = -1e30f;
                if (col > qr1)     s[nt][2] = -1e30f;
                if (col + 1 > qr1) s[nt][3] = -1e30f;
            }
        }

        float tm0 = -1e30f, tm1 = -1e30f;
#pragma unroll
        for (int nt = 0; nt < 8; nt++) {
            tm0 = fmaxf(tm0, fmaxf(s[nt][0], s[nt][1]));
            tm1 = fmaxf(tm1, fmaxf(s[nt][2], s[nt][3]));
        }
        tm0 = fmaxf(tm0, __shfl_xor_sync(0xffffffff, tm0, 1));
        tm0 = fmaxf(tm0, __shfl_xor_sync(0xffffffff, tm0, 2));
        tm1 = fmaxf(tm1, __shfl_xor_sync(0xffffffff, tm1, 1));
        tm1 = fmaxf(tm1, __shfl_xor_sync(0xffffffff, tm1, 2));
        float nm0 = fmaxf(m0, tm0);
        float nm1 = fmaxf(m1, tm1);
        float cr0 = ex2f(m0 - nm0);
        float cr1 = ex2f(m1 - nm1);
        m0 = nm0; m1 = nm1;
        l0 *= cr0; l1 *= cr1;
#pragma unroll
        for (int nt = 0; nt < 8; nt++) {
            oacc[nt][0] *= cr0; oacc[nt][1] *= cr0;
            oacc[nt][2] *= cr1; oacc[nt][3] *= cr1;
        }
#pragma unroll
        for (int nt = 0; nt < 8; nt++) {
            s[nt][0] = ex2f(s[nt][0] - nm0);
            s[nt][1] = ex2f(s[nt][1] - nm0);
            s[nt][2] = ex2f(s[nt][2] - nm1);
            s[nt][3] = ex2f(s[nt][3] - nm1);
            l0 += s[nt][0] + s[nt][1];
            l1 += s[nt][2] + s[nt][3];
        }

        // O += P @ V (P in registers, k-permuted)
#pragma unroll
        for (int kc = 0; kc < 8; kc++) {
            uint32_t pa[4];
            pa[0] = f2tf32(s[kc][0]);
            pa[1] = f2tf32(s[kc][2]);
            pa[2] = f2tf32(s[kc][1]);
            pa[3] = f2tf32(s[kc][3]);
#pragma unroll
            for (int nt = 0; nt < 8; nt++) {
                uint2 bb = *(const uint2*)&Vt[nt * 8 + g][kc * 8 + 2 * c];
                uint32_t bf[2] = {bb.x, bb.y};
                mma_tf32(oacc[nt], pa, bf);
            }
        }
    }

    l0 += __shfl_xor_sync(0xffffffff, l0, 1);
    l0 += __shfl_xor_sync(0xffffffff, l0, 2);
    l1 += __shfl_xor_sync(0xffffffff, l1, 1);
    l1 += __shfl_xor_sync(0xffffffff, l1, 2);
    const float inv0 = 1.f / l0;
    const float inv1 = 1.f / l1;

    const int bb = bh >> 5, h = bh & 31;
    const int qr = qt * 128 + rb + g;
    uint32_t* o0 = (uint32_t*)g_ao + ((size_t)(bb * LSEQ + qr)) * DMODEL + (size_t)h * HDIM;
    uint32_t* o1 = o0 + (size_t)8 * DMODEL;
#pragma unroll
    for (int nt = 0; nt < 8; nt++) {
        uint2 r0 = make_uint2(f2tf32(oacc[nt][0] * inv0), f2tf32(oacc[nt][1] * inv0));
        uint2 r1 = make_uint2(f2tf32(oacc[nt][2] * inv1), f2tf32(oacc[nt][3] * inv1));
        *(uint2*)(o0 + nt * 8 + 2 * c) = r0;
        *(uint2*)(o1 + nt * 8 + 2 * c) = r1;
    }
}

// ---------------------------------------------------------------------------
extern "C" void kernel_launch(void* const* d_in, const int* in_sizes, int n_in,
                              void* d_out, int out_size) {
    const float* x    = (const float*)d_in[0];
    const float* wqkv = (const float*)d_in[1];
    const float* wo   = (const float*)d_in[2];
    float* out        = (float*)d_out;

    float *qkv, *xc, *wqc, *woc, *ao;
    cudaGetSymbolAddress((void**)&qkv, g_qkv);
    cudaGetSymbolAddress((void**)&xc,  g_x);
    cudaGetSymbolAddress((void**)&wqc, g_wq);
    cudaGetSymbolAddress((void**)&woc, g_wo);
    cudaGetSymbolAddress((void**)&ao,  g_ao);

    static bool attr_set = false;
    if (!attr_set) {
        cudaFuncSetAttribute(k_flash_attn_mma,
                             cudaFuncAttributeMaxDynamicSharedMemorySize, FA_SMEM);
        cudaFuncSetAttribute(k_gemm_tf32,
                             cudaFuncAttributeMaxDynamicSharedMemorySize, GEMM_SMEM);
        attr_set = true;
    }

    // 0) pre-convert inputs to tf32 bits
    {
        int n4;
        n4 = MROWS * DMODEL / 4;  k_cvt<<<(n4 + 255) / 256, 256>>>(x, xc, n4);
        n4 = NQKV * DMODEL / 4;   k_cvt<<<(n4 + 255) / 256, 256>>>(wqkv, wqc, n4);
        n4 = DMODEL * DMODEL / 4; k_cvt<<<(n4 + 255) / 256, 256>>>(wo, woc, n4);
    }
    // 1) QKV projection
    {
        dim3 grid(NQKV / 128, MROWS / 128);
        k_gemm_tf32<<<grid, 128, GEMM_SMEM>>>((const uint32_t*)xc,
                                              (const uint32_t*)wqc, qkv,
                                              NQKV, DMODEL);
    }
    // 2) RoPE + split (+ tf32 conversion + V tile transpose)
    {
        int total = MROWS * NHEAD * 32;
        k_rope_split<<<(total + 255) / 256, 256>>>();
    }
    // 3) Flash attention
    {
        dim3 grid(LSEQ / 128, BSZ * NHEAD);
        k_flash_attn_mma<<<grid, 256, FA_SMEM>>>();
    }
    // 4) Output projection
    {
        dim3 grid(DMODEL / 128, MROWS / 128);
        k_gemm_tf32<<<grid, 128, GEMM_SMEM>>>((const uint32_t*)ao,
                                              (const uint32_t*)woc, out,
                                              DMODEL, DMODEL);
    }
}